// round 4
// baseline (speedup 1.0000x reference)
#include <cuda_runtime.h>
#include <math.h>

#define NN 50000
#define NE 800000
#define EL (NE + NN)          // edges + self loops = 850000
#define UF 64
#define NG 512

// ---------------- scratch (static device globals; no allocation) ----------------
__device__ float d_h[NN * UF];      // linear output per layer
__device__ float d_x[NN * UF];      // activated node features
__device__ float d_agg[NN * UF];    // aggregation accumulator
__device__ float d_as[NN];          // alpha_src per node
__device__ float d_ad[NN];          // alpha_dst per node
__device__ float d_ex[EL];          // exp(leakyrelu(e)) per edge
__device__ float d_denom[NN];       // softmax denominator per node
__device__ float d_dinv[NN];        // degree, then rsqrt(degree)
__device__ float d_pool[2 * NG];    // per-graph sums (branch 0 / 1)
__device__ float d_cnt[2 * NG];     // per-graph node counts

// ---------------- GAT input linear: h = x@W (9->64), alpha_s, alpha_d ----------------
__global__ void k_gat_linear(const float* __restrict__ x, const float* __restrict__ Wg,
                             const float* __restrict__ a_s, const float* __restrict__ a_d) {
    __shared__ float sW[9 * 64];
    __shared__ float sas[64], sad[64];
    __shared__ float s2[4][2][2];
    int tid = threadIdx.x;                     // 256 threads, 4 nodes/block
    for (int i = tid; i < 9 * 64; i += 256) sW[i] = Wg[i];
    if (tid < 64) { sas[tid] = a_s[tid]; sad[tid] = a_d[tid]; }
    __syncthreads();

    int f = tid & 63, grp = tid >> 6;
    int n = blockIdx.x * 4 + grp;              // 12500*4 = 50000 exactly
    const float* xr = x + n * 9;
    float hf = 0.f;
#pragma unroll
    for (int k = 0; k < 9; k++) hf = fmaf(xr[k], sW[k * 64 + f], hf);
    d_h[n * 64 + f] = hf;

    float ps = hf * sas[f], pd = hf * sad[f];
#pragma unroll
    for (int o = 16; o > 0; o >>= 1) {
        ps += __shfl_down_sync(0xffffffffu, ps, o);
        pd += __shfl_down_sync(0xffffffffu, pd, o);
    }
    int w = (tid >> 5) & 1;
    if ((tid & 31) == 0) { s2[grp][w][0] = ps; s2[grp][w][1] = pd; }
    __syncthreads();
    if (f == 0) {
        d_as[n] = s2[grp][0][0] + s2[grp][1][0];
        d_ad[n] = s2[grp][0][1] + s2[grp][1][1];
    }
}

// ---------------- GAT edge pass: ex = exp(lrelu(as[src]+ad[dst])), denom, degree --------
__global__ void k_gat_edge(const int* __restrict__ ei) {
    int e = blockIdx.x * blockDim.x + threadIdx.x;
    if (e >= EL) return;
    int src, dst;
    if (e < NE) { src = ei[e]; dst = ei[NE + e]; }
    else        { src = dst = e - NE; }            // self loop
    float v = d_as[src] + d_ad[dst];
    v = v > 0.f ? v : 0.2f * v;                    // leaky relu 0.2
    float ex = expf(v);                            // unstabilized softmax (bounded, see notes)
    d_ex[e] = ex;
    atomicAdd(&d_denom[dst], ex);
    atomicAdd(&d_dinv[dst], 1.0f);                 // degree (incl. self loop)
}

// ---------------- weighted aggregation: agg[dst] += h[src]*coef (16 lanes/edge) --------
template <int MODE>   // 0 = GAT (softmax coef), 1 = GCN (dinv[src]*dinv[dst])
__global__ void k_agg(const int* __restrict__ ei) {
    int gt = blockIdx.x * 256 + threadIdx.x;       // EL*16 = 13.6M threads
    int e = gt >> 4;
    if (e >= EL) return;
    int t = gt & 15;
    int src, dst;
    if (e < NE) { src = ei[e]; dst = ei[NE + e]; }
    else        { src = dst = e - NE; }
    float c = (MODE == 0) ? (d_ex[e] / d_denom[dst])
                          : (d_dinv[src] * d_dinv[dst]);
    float4 hv = *(const float4*)(d_h + src * 64 + t * 4);
    float4 v = make_float4(hv.x * c, hv.y * c, hv.z * c, hv.w * c);
    atomicAdd((float4*)(d_agg + dst * 64 + t * 4), v);   // sm_90+ vector RED
}

// ---------------- node finish: x = tanh(agg + b); (GAT also finalizes dinv) -------------
template <int GAT>
__global__ void k_finish(const float* __restrict__ b) {
    int i = blockIdx.x * blockDim.x + threadIdx.x;
    if (i >= NN * UF) return;
    int f = i & 63;
    d_x[i] = tanhf(d_agg[i] + b[f]);
    if (GAT && f == 0) {
        int n = i >> 6;
        d_dinv[n] = rsqrtf(d_dinv[n]);             // deg >= 1 always (self loop)
    }
}

// ---------------- 64x64 GEMM: h = x @ W ----------------
__global__ void k_gemm64(const float* __restrict__ W) {
    __shared__ float sW[64 * 64];
    __shared__ float sx[16][64];
    int tid = threadIdx.x;                          // 256 threads, 16 nodes/block
    for (int i = tid; i < 4096; i += 256) sW[i] = W[i];
    int nb = blockIdx.x * 16;                       // 3125*16 = 50000 exactly
    for (int i = tid; i < 16 * 64; i += 256) {
        int r = i >> 6, c = i & 63;
        sx[r][c] = d_x[(nb + r) * 64 + c];
    }
    __syncthreads();
    int f = tid & 63, g = tid >> 6;
#pragma unroll
    for (int rr = 0; rr < 4; rr++) {
        int r = g * 4 + rr;
        float acc = 0.f;
#pragma unroll
        for (int k = 0; k < 64; k++) acc = fmaf(sx[r][k], sW[k * 64 + f], acc);
        d_h[(nb + r) * 64 + f] = acc;
    }
}

// ---------------- fused MLP (64->64->32->1) + mean-pool accumulation -------------------
__global__ void k_mlp(const int* __restrict__ batch,
                      const float* __restrict__ W1, const float* __restrict__ b1,
                      const float* __restrict__ W2, const float* __restrict__ b2,
                      const float* __restrict__ W3, const float* __restrict__ b3,
                      int which) {
    __shared__ float sW1[64 * 64];
    __shared__ float sW2[64 * 32];
    __shared__ float sW3[32], sb1[64], sb2[32];
    __shared__ float xr[64], y1[64], y2[32];
    int tid = threadIdx.x;                          // 64 threads
    for (int i = tid; i < 4096; i += 64) sW1[i] = W1[i];
    for (int i = tid; i < 2048; i += 64) sW2[i] = W2[i];
    if (tid < 32) { sW3[tid] = W3[tid]; sb2[tid] = b2[tid]; }
    sb1[tid] = b1[tid];
    float b3v = b3[0];
    __syncthreads();

    for (int it = 0; it < 16; it++) {
        int n = blockIdx.x * 16 + it;               // 3125*16 = 50000 exactly
        xr[tid] = d_x[n * 64 + tid];
        __syncthreads();
        float a1 = sb1[tid];
#pragma unroll
        for (int k = 0; k < 64; k++) a1 = fmaf(xr[k], sW1[k * 64 + tid], a1);
        y1[tid] = tanhf(a1);
        __syncthreads();
        if (tid < 32) {
            float a2 = sb2[tid];
#pragma unroll
            for (int k = 0; k < 64; k++) a2 = fmaf(y1[k], sW2[k * 32 + tid], a2);
            y2[tid] = tanhf(a2);
        }
        __syncthreads();
        if (tid < 32) {
            float p = y2[tid] * sW3[tid];
#pragma unroll
            for (int o = 16; o > 0; o >>= 1) p += __shfl_down_sync(0xffffffffu, p, o);
            if (tid == 0) {
                float v = p + b3v;
                int g = batch[n];
                atomicAdd(&d_pool[which * NG + g], v);
                atomicAdd(&d_cnt[which * NG + g], 1.0f);
            }
        }
        __syncthreads();
    }
}

// ---------------- final: sigmoid(mean_b - mean_a) ----------------
__global__ void k_final(float* __restrict__ out) {
    int g = blockIdx.x * blockDim.x + threadIdx.x;
    if (g >= NG) return;
    float ua = d_pool[g]      / fmaxf(d_cnt[g], 1.0f);
    float ub = d_pool[NG + g] / fmaxf(d_cnt[NG + g], 1.0f);
    out[g] = 1.0f / (1.0f + expf(-(ub - ua)));
}

// =======================================================================================
extern "C" void kernel_launch(void* const* d_in, const int* in_sizes, int n_in,
                              void* d_out, int out_size) {
    const float* x_a   = (const float*)d_in[0];
    const float* x_b   = (const float*)d_in[1];
    const int*   ei_a  = (const int*)d_in[2];
    const int*   ei_b  = (const int*)d_in[3];
    const int*   bat_a = (const int*)d_in[4];
    const int*   bat_b = (const int*)d_in[5];
    const float* W_gat = (const float*)d_in[6];
    const float* a_src = (const float*)d_in[7];
    const float* a_dst = (const float*)d_in[8];
    const float* b_gat = (const float*)d_in[9];
    const float* W_gcn = (const float*)d_in[10];   // [2,64,64]
    const float* b_gcn = (const float*)d_in[11];   // [2,64]
    const float* W1    = (const float*)d_in[12];
    const float* b1    = (const float*)d_in[13];
    const float* W2    = (const float*)d_in[14];
    const float* b2    = (const float*)d_in[15];
    const float* W3    = (const float*)d_in[16];
    const float* b3    = (const float*)d_in[17];
    float* out = (float*)d_out;

    void *p_agg, *p_denom, *p_dinv, *p_pool, *p_cnt;
    cudaGetSymbolAddress(&p_agg,   d_agg);
    cudaGetSymbolAddress(&p_denom, d_denom);
    cudaGetSymbolAddress(&p_dinv,  d_dinv);
    cudaGetSymbolAddress(&p_pool,  d_pool);
    cudaGetSymbolAddress(&p_cnt,   d_cnt);

    cudaMemsetAsync(p_pool, 0, 2 * NG * sizeof(float));
    cudaMemsetAsync(p_cnt,  0, 2 * NG * sizeof(float));

    const int EDGE_BLKS = (EL + 255) / 256;        // 3321
    const int AGG_BLKS  = (EL * 16 + 255) / 256;   // 53125
    const int FIN_BLKS  = (NN * UF + 255) / 256;   // 12500

    for (int br = 0; br < 2; br++) {
        const float* x   = br ? x_b   : x_a;
        const int*   ei  = br ? ei_b  : ei_a;
        const int*   bat = br ? bat_b : bat_a;

        cudaMemsetAsync(p_denom, 0, NN * sizeof(float));
        cudaMemsetAsync(p_dinv,  0, NN * sizeof(float));
        cudaMemsetAsync(p_agg,   0, NN * UF * sizeof(float));

        k_gat_linear<<<NN / 4, 256>>>(x, W_gat, a_src, a_dst);
        k_gat_edge<<<EDGE_BLKS, 256>>>(ei);
        k_agg<0><<<AGG_BLKS, 256>>>(ei);
        k_finish<1><<<FIN_BLKS, 256>>>(b_gat);

        for (int l = 0; l < 2; l++) {
            k_gemm64<<<NN / 16, 256>>>(W_gcn + l * 64 * 64);
            cudaMemsetAsync(p_agg, 0, NN * UF * sizeof(float));
            k_agg<1><<<AGG_BLKS, 256>>>(ei);
            k_finish<0><<<FIN_BLKS, 256>>>(b_gcn + l * 64);
        }

        k_mlp<<<NN / 16, 64>>>(bat, W1, b1, W2, b2, W3, b3, br);
    }

    k_final<<<2, 256>>>(out);
}

// round 8
// speedup vs baseline: 1.9629x; 1.9629x over previous
#include <cuda_runtime.h>
#include <math.h>

#define NN 50000
#define NE 800000
#define UF 64
#define NG 512
#define SCAN_B 49              // ceil(50000/1024)

// ---------------- scratch (static device globals; no allocation) ----------------
__device__ float d_h[NN * UF];      // linear output per layer (GCN: pre-scaled by dinv)
__device__ float d_x[NN * UF];      // activated node features
__device__ float d_as[NN];          // alpha_src per node
__device__ float d_ad[NN];          // alpha_dst per node
__device__ float d_dinv[NN];        // rsqrt(in-degree incl self)
__device__ int   d_deg[NN];         // in-degree histogram (excl self)
__device__ int   d_rowptr[NN + 1];  // CSR row pointers
__device__ int   d_bsum[64];        // scan block sums
__device__ int   d_cnt2[NN];        // scatter cursors
__device__ int   d_csrc[NE];        // CSR src indices (sorted by dst)
__device__ float d_pool[2 * NG];    // per-graph sums
__device__ float d_cnt[2 * NG];     // per-graph node counts

__device__ __forceinline__ float tanh_fast(float x) {
    float e = __expf(2.0f * x);
    return 1.0f - __fdividef(2.0f, e + 1.0f);   // exact ±1 saturation at |x| large
}

// ---------------- GAT input linear: h = x@W (9->64), alpha_s, alpha_d ----------------
__global__ void k_gat_linear(const float* __restrict__ x, const float* __restrict__ Wg,
                             const float* __restrict__ a_s, const float* __restrict__ a_d) {
    __shared__ float sW[9 * 64];
    __shared__ float sas[64], sad[64];
    __shared__ float s2[4][2][2];
    int tid = threadIdx.x;                     // 256 threads, 4 nodes/block
    for (int i = tid; i < 9 * 64; i += 256) sW[i] = Wg[i];
    if (tid < 64) { sas[tid] = a_s[tid]; sad[tid] = a_d[tid]; }
    __syncthreads();

    int f = tid & 63, grp = tid >> 6;
    int n = blockIdx.x * 4 + grp;              // 12500*4 = 50000 exactly
    const float* xr = x + n * 9;
    float hf = 0.f;
#pragma unroll
    for (int k = 0; k < 9; k++) hf = fmaf(xr[k], sW[k * 64 + f], hf);
    d_h[n * 64 + f] = hf;

    float ps = hf * sas[f], pd = hf * sad[f];
#pragma unroll
    for (int o = 16; o > 0; o >>= 1) {
        ps += __shfl_down_sync(0xffffffffu, ps, o);
        pd += __shfl_down_sync(0xffffffffu, pd, o);
    }
    int w = (tid >> 5) & 1;
    if ((tid & 31) == 0) { s2[grp][w][0] = ps; s2[grp][w][1] = pd; }
    __syncthreads();
    if (f == 0) {
        d_as[n] = s2[grp][0][0] + s2[grp][1][0];
        d_ad[n] = s2[grp][0][1] + s2[grp][1][1];
    }
}

// ---------------- CSR build ----------------
__global__ void k_hist(const int* __restrict__ ei) {
    int e = blockIdx.x * blockDim.x + threadIdx.x;
    if (e >= NE) return;
    atomicAdd(&d_deg[ei[NE + e]], 1);
}

__global__ void k_scan1() {
    __shared__ int s[1024];
    int t = threadIdx.x, i = blockIdx.x * 1024 + t;
    int v = (i < NN) ? d_deg[i] : 0;
    s[t] = v;
    __syncthreads();
    for (int o = 1; o < 1024; o <<= 1) {
        int a = (t >= o) ? s[t - o] : 0;
        __syncthreads();
        s[t] += a;
        __syncthreads();
    }
    if (i < NN) d_rowptr[i] = s[t] - v;        // exclusive within block
    if (t == 1023) d_bsum[blockIdx.x] = s[1023];
}

__global__ void k_scan2() {
    if (threadIdx.x == 0) {
        int acc = 0;
        for (int i = 0; i < SCAN_B; i++) { int v = d_bsum[i]; d_bsum[i] = acc; acc += v; }
    }
}

__global__ void k_scan3() {
    int i = blockIdx.x * 1024 + threadIdx.x;
    if (i < NN) d_rowptr[i] += d_bsum[i >> 10];
    if (i == 0) d_rowptr[NN] = NE;
}

__global__ void k_scatter(const int* __restrict__ ei) {
    int e = blockIdx.x * blockDim.x + threadIdx.x;
    if (e >= NE) return;
    int src = ei[e], dst = ei[NE + e];
    int pos = d_rowptr[dst] + atomicAdd(&d_cnt2[dst], 1);
    d_csrc[pos] = src;
}

// ---------------- fused GAT aggregation: warp per node, one pass softmax --------------
__global__ void k_gat_agg(const float* __restrict__ b) {
    int wid = (blockIdx.x * blockDim.x + threadIdx.x) >> 5;
    if (wid >= NN) return;
    int lane = threadIdx.x & 31;
    int n = wid;
    int rs = d_rowptr[n], re = d_rowptr[n + 1];
    float adn = d_ad[n];
    int f = lane * 2;

    // self loop
    float v = d_as[n] + adn;
    v = v > 0.f ? v : 0.2f * v;
    float ex = __expf(v);
    float2 hv = *(const float2*)(d_h + n * 64 + f);
    float accx = ex * hv.x, accy = ex * hv.y, den = ex;

#pragma unroll 4
    for (int e = rs; e < re; e++) {
        int src = d_csrc[e];
        float vv = d_as[src] + adn;
        vv = vv > 0.f ? vv : 0.2f * vv;
        float exx = __expf(vv);
        float2 h2 = *(const float2*)(d_h + src * 64 + f);
        accx = fmaf(exx, h2.x, accx);
        accy = fmaf(exx, h2.y, accy);
        den += exx;
    }
    float inv = __fdividef(1.0f, den);
    float o0 = tanh_fast(fmaf(accx, inv, b[f]));
    float o1 = tanh_fast(fmaf(accy, inv, b[f + 1]));
    *(float2*)(d_x + n * 64 + f) = make_float2(o0, o1);
    if (lane == 0) d_dinv[n] = rsqrtf((float)(re - rs + 1));
}

// ---------------- fused GCN aggregation: warp per node (h pre-scaled by dinv) ---------
__global__ void k_gcn_agg(const float* __restrict__ b) {
    int wid = (blockIdx.x * blockDim.x + threadIdx.x) >> 5;
    if (wid >= NN) return;
    int lane = threadIdx.x & 31;
    int n = wid;
    int rs = d_rowptr[n], re = d_rowptr[n + 1];
    int f = lane * 2;

    float2 hv = *(const float2*)(d_h + n * 64 + f);   // self loop (pre-scaled)
    float accx = hv.x, accy = hv.y;

#pragma unroll 4
    for (int e = rs; e < re; e++) {
        int src = d_csrc[e];
        float2 h2 = *(const float2*)(d_h + src * 64 + f);
        accx += h2.x;
        accy += h2.y;
    }
    float di = d_dinv[n];
    float o0 = tanh_fast(fmaf(accx, di, b[f]));
    float o1 = tanh_fast(fmaf(accy, di, b[f + 1]));
    *(float2*)(d_x + n * 64 + f) = make_float2(o0, o1);
}

// ---------------- 64x64 GEMM with dinv pre-scale epilogue: h = (x @ W) * dinv ---------
__global__ void k_gemm64(const float* __restrict__ W) {
    __shared__ float sW[64 * 64];
    __shared__ float sx[16][64];
    __shared__ float sdi[16];
    int tid = threadIdx.x;                          // 256 threads, 16 nodes/block
    for (int i = tid; i < 4096; i += 256) sW[i] = W[i];
    int nb = blockIdx.x * 16;                       // 3125*16 = 50000 exactly
    for (int i = tid; i < 16 * 64; i += 256) {
        int r = i >> 6, c = i & 63;
        sx[r][c] = d_x[(nb + r) * 64 + c];
    }
    if (tid < 16) sdi[tid] = d_dinv[nb + tid];
    __syncthreads();
    int f = tid & 63, g = tid >> 6;
#pragma unroll
    for (int rr = 0; rr < 4; rr++) {
        int r = g * 4 + rr;
        float acc = 0.f;
#pragma unroll
        for (int k = 0; k < 64; k++) acc = fmaf(sx[r][k], sW[k * 64 + f], acc);
        d_h[(nb + r) * 64 + f] = acc * sdi[r];
    }
}

// ---------------- fused MLP (64->64->32->1) + mean-pool accumulation -------------------
__global__ void k_mlp(const int* __restrict__ batch,
                      const float* __restrict__ W1, const float* __restrict__ b1,
                      const float* __restrict__ W2, const float* __restrict__ b2,
                      const float* __restrict__ W3, const float* __restrict__ b3,
                      int which) {
    __shared__ float sW1[64 * 64];
    __shared__ float sW2[64 * 32];
    __shared__ float sW3[32], sb1[64], sb2[32];
    __shared__ float xr[64], y1[64], y2[32];
    int tid = threadIdx.x;                          // 64 threads
    for (int i = tid; i < 4096; i += 64) sW1[i] = W1[i];
    for (int i = tid; i < 2048; i += 64) sW2[i] = W2[i];
    if (tid < 32) { sW3[tid] = W3[tid]; sb2[tid] = b2[tid]; }
    sb1[tid] = b1[tid];
    float b3v = b3[0];
    __syncthreads();

    for (int it = 0; it < 16; it++) {
        int n = blockIdx.x * 16 + it;               // 3125*16 = 50000 exactly
        xr[tid] = d_x[n * 64 + tid];
        __syncthreads();
        float a1 = sb1[tid];
#pragma unroll
        for (int k = 0; k < 64; k++) a1 = fmaf(xr[k], sW1[k * 64 + tid], a1);
        y1[tid] = tanh_fast(a1);
        __syncthreads();
        if (tid < 32) {
            float a2 = sb2[tid];
#pragma unroll
            for (int k = 0; k < 64; k++) a2 = fmaf(y1[k], sW2[k * 32 + tid], a2);
            y2[tid] = tanh_fast(a2);
        }
        __syncthreads();
        if (tid < 32) {
            float p = y2[tid] * sW3[tid];
#pragma unroll
            for (int o = 16; o > 0; o >>= 1) p += __shfl_down_sync(0xffffffffu, p, o);
            if (tid == 0) {
                float v = p + b3v;
                int g = batch[n];
                atomicAdd(&d_pool[which * NG + g], v);
                atomicAdd(&d_cnt[which * NG + g], 1.0f);
            }
        }
        __syncthreads();
    }
}

// ---------------- final: sigmoid(mean_b - mean_a) ----------------
__global__ void k_final(float* __restrict__ out) {
    int g = blockIdx.x * blockDim.x + threadIdx.x;
    if (g >= NG) return;
    float ua = d_pool[g]      / fmaxf(d_cnt[g], 1.0f);
    float ub = d_pool[NG + g] / fmaxf(d_cnt[NG + g], 1.0f);
    out[g] = __fdividef(1.0f, 1.0f + __expf(-(ub - ua)));
}

// =======================================================================================
extern "C" void kernel_launch(void* const* d_in, const int* in_sizes, int n_in,
                              void* d_out, int out_size) {
    const float* x_a   = (const float*)d_in[0];
    const float* x_b   = (const float*)d_in[1];
    const int*   ei_a  = (const int*)d_in[2];
    const int*   ei_b  = (const int*)d_in[3];
    const int*   bat_a = (const int*)d_in[4];
    const int*   bat_b = (const int*)d_in[5];
    const float* W_gat = (const float*)d_in[6];
    const float* a_src = (const float*)d_in[7];
    const float* a_dst = (const float*)d_in[8];
    const float* b_gat = (const float*)d_in[9];
    const float* W_gcn = (const float*)d_in[10];   // [2,64,64]
    const float* b_gcn = (const float*)d_in[11];   // [2,64]
    const float* W1    = (const float*)d_in[12];
    const float* b1    = (const float*)d_in[13];
    const float* W2    = (const float*)d_in[14];
    const float* b2    = (const float*)d_in[15];
    const float* W3    = (const float*)d_in[16];
    const float* b3    = (const float*)d_in[17];
    float* out = (float*)d_out;

    void *p_deg, *p_cnt2, *p_pool, *p_cnt;
    cudaGetSymbolAddress(&p_deg,  d_deg);
    cudaGetSymbolAddress(&p_cnt2, d_cnt2);
    cudaGetSymbolAddress(&p_pool, d_pool);
    cudaGetSymbolAddress(&p_cnt,  d_cnt);

    cudaMemsetAsync(p_pool, 0, 2 * NG * sizeof(float));
    cudaMemsetAsync(p_cnt,  0, 2 * NG * sizeof(float));

    const int E_BLKS   = (NE + 255) / 256;          // 3125
    const int AGG_BLKS = (NN * 32 + 255) / 256;     // 6250

    for (int br = 0; br < 2; br++) {
        const float* x   = br ? x_b   : x_a;
        const int*   ei  = br ? ei_b  : ei_a;
        const int*   bat = br ? bat_b : bat_a;

        // CSR build (reused by GAT + both GCN layers)
        cudaMemsetAsync(p_deg,  0, NN * sizeof(int));
        cudaMemsetAsync(p_cnt2, 0, NN * sizeof(int));
        k_hist<<<E_BLKS, 256>>>(ei);
        k_scan1<<<SCAN_B, 1024>>>();
        k_scan2<<<1, 32>>>();
        k_scan3<<<SCAN_B, 1024>>>();
        k_scatter<<<E_BLKS, 256>>>(ei);

        // GAT layer (linear + fused softmax-agg + bias + tanh + dinv)
        k_gat_linear<<<NN / 4, 256>>>(x, W_gat, a_src, a_dst);
        k_gat_agg<<<AGG_BLKS, 256>>>(b_gat);

        // 2 GCN layers (gemm w/ dinv pre-scale + fused gather-agg + bias + tanh)
        for (int l = 0; l < 2; l++) {
            k_gemm64<<<NN / 16, 256>>>(W_gcn + l * 64 * 64);
            k_gcn_agg<<<AGG_BLKS, 256>>>(b_gcn + l * 64);
        }

        k_mlp<<<NN / 16, 64>>>(bat, W1, b1, W2, b2, W3, b3, br);
    }

    k_final<<<2, 256>>>(out);
}